// round 5
// baseline (speedup 1.0000x reference)
#include <cuda_runtime.h>
#include <cuda_fp16.h>
#include <cstdint>

// ============================================================================
// RBF: out[i][j] = exp(-0.5 * ||x_i - y_j||^2 / sigma^2), N=M=8192, D=64.
// sqd = xn_i + yn_j - 2*(x_i . y_j). Cross term via mma.sync fp16 HMMA with
// exact fp16 hi/lo split folded into K (3-term: hi*hi + hi*lo + lo*hi, K=192):
//   A' = [x_hi, x_hi, x_lo],  B' = [y_hi, y_lo, y_hi]
// Error from dropped lo*lo ~ 2^-22 relative: far under the 1e-3 gate.
// R4 fix: B ldmatrix must be NON-trans — K-major sB rows already give the
// col-major B fragment (consecutive k at fixed n) directly.
// ============================================================================

#define NROWS 8192
#define DDIM 64
#define KX 192            // split-fp16 K (3 segments of 64)
#define LDA 200           // padded smem row stride in halves (400 B)
#define TILE 128

// -------- device scratch (static; allocation-guard safe) --------
__device__ __align__(16) __half g_A[(size_t)NROWS * KX];   // 3 MB
__device__ __align__(16) __half g_B[(size_t)NROWS * KX];   // 3 MB
__device__ float g_xn[NROWS];
__device__ float g_yn[NROWS];

__device__ __forceinline__ uint32_t smem_u32(const void* p) {
    uint32_t a;
    asm("{ .reg .u64 t; cvta.to.shared.u64 t, %1; cvt.u32.u64 %0, t; }" : "=r"(a) : "l"(p));
    return a;
}

__device__ __forceinline__ void mma16816(float* d, const uint32_t* a, const uint32_t* b) {
    asm volatile(
        "mma.sync.aligned.m16n8k16.row.col.f32.f16.f16.f32 "
        "{%0,%1,%2,%3}, {%4,%5,%6,%7}, {%8,%9}, {%0,%1,%2,%3};"
        : "+f"(d[0]), "+f"(d[1]), "+f"(d[2]), "+f"(d[3])
        : "r"(a[0]), "r"(a[1]), "r"(a[2]), "r"(a[3]), "r"(b[0]), "r"(b[1]));
}

// ============================================================================
// prep: fp32 -> (hi, lo) fp16 split, build K=192 operands + fp32 norms
// ============================================================================
__global__ void prep_kernel(const float* __restrict__ x, const float* __restrict__ y) {
    int wid = threadIdx.x >> 5, lane = threadIdx.x & 31;
    int rg = blockIdx.x * 8 + wid;          // 8 warps/block, one row per warp
    bool isx = rg < NROWS;
    int row = isx ? rg : rg - NROWS;
    const float* src = isx ? x : y;

    float v0 = src[(size_t)row * DDIM + lane];
    float v1 = src[(size_t)row * DDIM + lane + 32];
    __half h0 = __float2half_rn(v0);
    __half h1 = __float2half_rn(v1);
    __half l0 = __float2half_rn(v0 - __half2float(h0));
    __half l1 = __float2half_rn(v1 - __half2float(h1));

    __half* dst = (isx ? g_A : g_B) + (size_t)row * KX;
    if (isx) {  // A' = [hi, hi, lo]
        dst[lane]       = h0; dst[lane + 32]  = h1;
        dst[64 + lane]  = h0; dst[96 + lane]  = h1;
        dst[128 + lane] = l0; dst[160 + lane] = l1;
    } else {    // B' = [hi, lo, hi]
        dst[lane]       = h0; dst[lane + 32]  = h1;
        dst[64 + lane]  = l0; dst[96 + lane]  = l1;
        dst[128 + lane] = h0; dst[160 + lane] = h1;
    }

    float s = v0 * v0 + v1 * v1;
    #pragma unroll
    for (int o = 16; o; o >>= 1) s += __shfl_xor_sync(0xffffffffu, s, o);
    if (lane == 0) (isx ? g_xn : g_yn)[row] = s;
}

// ============================================================================
// main: 128x128 output tile per CTA, 8 warps (2x4), warp tile 64x32,
// whole K=192 staged in smem (no k-mainloop), fused RBF epilogue.
// ============================================================================
#define SMEM_HALVES (2 * TILE * LDA)
#define SMEM_TOTAL  (SMEM_HALVES * 2 + 2 * TILE * 4)   // 102400 + 1024 B

__global__ __launch_bounds__(256, 2)
void rbf_kernel(const float* __restrict__ sigma, float* __restrict__ out) {
    extern __shared__ __half smem[];
    __half* sA = smem;
    __half* sB = smem + TILE * LDA;
    float*  s_xn = (float*)(smem + SMEM_HALVES);
    float*  s_yn = s_xn + TILE;

    int tid = threadIdx.x;
    int tile_n = blockIdx.x, tile_m = blockIdx.y;

    // stage norms
    if (tid < TILE)       s_xn[tid]        = g_xn[tile_m * TILE + tid];
    else                  s_yn[tid - TILE] = g_yn[tile_n * TILE + tid - TILE];

    // stage operand tiles (row-major, padded stride LDA)
    const uint4* gA = (const uint4*)(g_A + (size_t)tile_m * TILE * KX);
    const uint4* gB = (const uint4*)(g_B + (size_t)tile_n * TILE * KX);
    #pragma unroll
    for (int i = tid; i < TILE * (KX / 8); i += 256) {
        int r = i / 24, c = i % 24;
        *(uint4*)(sA + r * LDA + c * 8) = gA[i];
    }
    #pragma unroll
    for (int i = tid; i < TILE * (KX / 8); i += 256) {
        int r = i / 24, c = i % 24;
        *(uint4*)(sB + r * LDA + c * 8) = gB[i];
    }
    __syncthreads();

    int w = tid >> 5, lane = tid & 31;
    int warp_m = w >> 2, warp_n = w & 3;
    int m_base = warp_m * 64, n_base = warp_n * 32;
    int g = lane >> 3, tr = lane & 7;

    // ldmatrix base addresses (bytes)
    // A (.x4): g0 rows m..m+7 @k, g1 rows m+8..15 @k, g2 rows m..7 @k+8, g3 rows m+8..15 @k+8
    uint32_t a_sm = smem_u32(sA);
    uint32_t b_sm = smem_u32(sB);
    uint32_t aAddr = a_sm + (uint32_t)(((m_base + (g & 1) * 8 + tr) * LDA + (g >> 1) * 8) * 2);
    // B (.x4, NON-trans): g0 rows n..n+7 @k, g1 rows n..n+7 @k+8, g2 rows n+8..15 @k, g3 @k+8
    uint32_t bAddr = b_sm + (uint32_t)(((n_base + (g >> 1) * 8 + tr) * LDA + (g & 1) * 8) * 2);

    float acc[4][4][4];
    #pragma unroll
    for (int mf = 0; mf < 4; ++mf)
        #pragma unroll
        for (int nf = 0; nf < 4; ++nf)
            #pragma unroll
            for (int r = 0; r < 4; ++r) acc[mf][nf][r] = 0.f;

    #pragma unroll 2
    for (int ks = 0; ks < KX / 16; ++ks) {
        uint32_t kb = (uint32_t)(ks * 16 * 2);   // byte offset along k

        uint32_t a_frag[4][4];
        #pragma unroll
        for (int mf = 0; mf < 4; ++mf) {
            uint32_t addr = aAddr + (uint32_t)(mf * 16 * LDA * 2) + kb;
            asm volatile("ldmatrix.sync.aligned.m8n8.x4.shared.b16 {%0,%1,%2,%3}, [%4];"
                : "=r"(a_frag[mf][0]), "=r"(a_frag[mf][1]),
                  "=r"(a_frag[mf][2]), "=r"(a_frag[mf][3])
                : "r"(addr));
        }
        uint32_t b_frag[4][2];
        #pragma unroll
        for (int p = 0; p < 2; ++p) {
            uint32_t addr = bAddr + (uint32_t)(p * 16 * LDA * 2) + kb;
            uint32_t r0, r1, r2, r3;
            // NON-trans: K-major rows already match the col-major B fragment.
            asm volatile("ldmatrix.sync.aligned.m8n8.x4.shared.b16 {%0,%1,%2,%3}, [%4];"
                : "=r"(r0), "=r"(r1), "=r"(r2), "=r"(r3)
                : "r"(addr));
            b_frag[2 * p][0] = r0;     b_frag[2 * p][1] = r1;
            b_frag[2 * p + 1][0] = r2; b_frag[2 * p + 1][1] = r3;
        }

        #pragma unroll
        for (int mf = 0; mf < 4; ++mf)
            #pragma unroll
            for (int nf = 0; nf < 4; ++nf)
                mma16816(acc[mf][nf], a_frag[mf], b_frag[nf]);
    }

    // fused epilogue: q = max(xn + yn - 2c, 0); out = exp2(q * -0.5/ln2/sigma^2)
    float sg = *sigma;
    float k2 = -0.7213475204444817f / (sg * sg);
    int r0 = lane >> 2;           // 0..7
    int c0 = (lane & 3) * 2;      // 0,2,4,6

    size_t out_row0 = (size_t)(tile_m * TILE + m_base + r0) * 8192u
                    + (size_t)(tile_n * TILE + n_base + c0);
    #pragma unroll
    for (int mf = 0; mf < 4; ++mf) {
        float xnA = s_xn[m_base + mf * 16 + r0];
        float xnB = s_xn[m_base + mf * 16 + r0 + 8];
        #pragma unroll
        for (int nf = 0; nf < 4; ++nf) {
            int col = n_base + nf * 8 + c0;
            float yn0 = s_yn[col], yn1 = s_yn[col + 1];
            float* d = acc[mf][nf];
            float q0 = fmaxf(fmaf(-2.f, d[0], xnA + yn0), 0.f);
            float q1 = fmaxf(fmaf(-2.f, d[1], xnA + yn1), 0.f);
            float q2 = fmaxf(fmaf(-2.f, d[2], xnB + yn0), 0.f);
            float q3 = fmaxf(fmaf(-2.f, d[3], xnB + yn1), 0.f);
            float2 o01, o23;
            o01.x = exp2f(q0 * k2); o01.y = exp2f(q1 * k2);
            o23.x = exp2f(q2 * k2); o23.y = exp2f(q3 * k2);
            size_t base = out_row0 + (size_t)(mf * 16) * 8192u + (size_t)(nf * 8);
            *reinterpret_cast<float2*>(out + base)               = o01;
            *reinterpret_cast<float2*>(out + base + 8u * 8192u)  = o23;
        }
    }
}

// ============================================================================
extern "C" void kernel_launch(void* const* d_in, const int* in_sizes, int n_in,
                              void* d_out, int out_size) {
    (void)in_sizes; (void)n_in; (void)out_size;
    const float* x     = (const float*)d_in[0];
    const float* y     = (const float*)d_in[1];
    const float* sigma = (const float*)d_in[2];
    float* out = (float*)d_out;

    cudaFuncSetAttribute(rbf_kernel, cudaFuncAttributeMaxDynamicSharedMemorySize, SMEM_TOTAL);

    prep_kernel<<<(2 * NROWS) / 8, 256>>>(x, y);
    rbf_kernel<<<dim3(NROWS / TILE, NROWS / TILE), 256, SMEM_TOTAL>>>(sigma, out);
}